// round 2
// baseline (speedup 1.0000x reference)
#include <cuda_runtime.h>
#include <math.h>
#include <stdint.h>

// Problem constants
constexpr int Bv  = 16;
constexpr int Cv  = 512;
constexpr int Lv  = 2048;
constexpr int Hv  = 8;
constexpr int Dhv = 64;          // C/H
constexpr long long MLL = (long long)Bv * Lv;   // 32768 rows

// ---------------- scratch (static device arrays; no dynamic alloc) -------
__device__ float g_Q[16777216];   // (B*L, C)
__device__ float g_K[16777216];
__device__ float g_V[16777216];
__device__ float g_O[16777216];   // attention output (B*L, C)
__device__ float g_Y[16777216];   // o @ Wo + bo
__device__ float g_U[33554432];   // (B*L, 2C)
__device__ float g_M[16777216];   // (B*L, C) MLP out
__device__ float g_S1[Bv*Cv], g_T1[Bv*Cv];
__device__ float g_S2[Bv*Cv], g_T2[Bv*Cv];

// ---------------- instance-norm stats over rows of x (B,C,L) -------------
// one block per (b,c); x row contiguous (length L)
__global__ void rowstats_kernel(const float* __restrict__ x,
                                const float* __restrict__ gamma,
                                const float* __restrict__ beta,
                                float* __restrict__ s, float* __restrict__ t)
{
    int row = blockIdx.x;                  // b*C + c
    const float4* p = (const float4*)(x + (size_t)row * Lv);
    float sum = 0.f, sq = 0.f;
    for (int i = threadIdx.x; i < Lv / 4; i += blockDim.x) {
        float4 v = p[i];
        sum += v.x + v.y + v.z + v.w;
        sq  += v.x*v.x + v.y*v.y + v.z*v.z + v.w*v.w;
    }
    __shared__ float ssum[8], ssq[8];
    for (int o = 16; o; o >>= 1) {
        sum += __shfl_down_sync(0xffffffffu, sum, o);
        sq  += __shfl_down_sync(0xffffffffu, sq,  o);
    }
    int wid = threadIdx.x >> 5, lane = threadIdx.x & 31;
    if (lane == 0) { ssum[wid] = sum; ssq[wid] = sq; }
    __syncthreads();
    if (wid == 0) {
        sum = lane < (blockDim.x >> 5) ? ssum[lane] : 0.f;
        sq  = lane < (blockDim.x >> 5) ? ssq[lane]  : 0.f;
        for (int o = 4; o; o >>= 1) {
            sum += __shfl_down_sync(0xffffffffu, sum, o);
            sq  += __shfl_down_sync(0xffffffffu, sq,  o);
        }
        if (lane == 0) {
            float mean = sum / (float)Lv;
            float var  = sq / (float)Lv - mean * mean;
            float rstd = rsqrtf(var + 1e-5f);
            int c = row % Cv;
            float sv = gamma[c] * rstd;
            s[row] = sv;
            t[row] = beta[c] - mean * sv;
        }
    }
}

// ---------------- instance-norm stats over columns of y (B*L, C) ---------
// normalizes y[b, :, c] over l.  grid = (C/32, B), block = 256 (32 c x 8 l)
__global__ void colstats_kernel(const float* __restrict__ y,
                                const float* __restrict__ gamma,
                                const float* __restrict__ beta,
                                float* __restrict__ s, float* __restrict__ t)
{
    int b  = blockIdx.y;
    int ci = threadIdx.x & 31;
    int lj = threadIdx.x >> 5;            // 0..7
    int c  = blockIdx.x * 32 + ci;
    const float* base = y + (size_t)b * Lv * Cv + c;
    float sum = 0.f, sq = 0.f;
    for (int l = lj; l < Lv; l += 8) {
        float v = base[(size_t)l * Cv];
        sum += v; sq += v * v;
    }
    __shared__ float S[8][32], Q[8][32];
    S[lj][ci] = sum; Q[lj][ci] = sq;
    __syncthreads();
    if (lj == 0) {
        #pragma unroll
        for (int j = 1; j < 8; j++) { sum += S[j][ci]; sq += Q[j][ci]; }
        float mean = sum / (float)Lv;
        float var  = sq / (float)Lv - mean * mean;
        float rstd = rsqrtf(var + 1e-5f);
        float sv = gamma[c] * rstd;
        s[b * Cv + c] = sv;
        t[b * Cv + c] = beta[c] - mean * sv;
    }
}

// ---------------- generic fp32 GEMM -------------------------------------
// Y[m,n] = act( sum_k A'[m,k] * W[k,n] + bias[n] )
// LAYOUT 0: A is (B, K, L) channels-first; m = b*L + l, reads contiguous in l
// LAYOUT 1: A is (M, K) row-major
// Optional per-(b,k) affine on A: A' = A*sA + tA  (fused instance norm)
// ACT 0: none.  ACT 1: QuickGELU u*sigmoid(1.702u)
#define BM_ 128
#define BN_ 128
#define BK_ 16

template<int LAYOUT, int ACT>
__global__ void __launch_bounds__(256)
gemm_kernel(const float* __restrict__ A, const float* __restrict__ W,
            const float* __restrict__ bias,
            const float* __restrict__ sA, const float* __restrict__ tA,
            float* __restrict__ Y, int N, int K)
{
    __shared__ float As[BK_][BM_ + 4];
    __shared__ float Bs[BK_][BN_];

    const int bm = blockIdx.y * BM_;
    const int bn = blockIdx.x * BN_;
    const int b  = bm / Lv;               // tile never crosses batch (L%BM==0)
    const int l0 = bm % Lv;
    const int tid = threadIdx.x;
    const int tx = tid & 15;              // n
    const int ty = tid >> 4;              // m

    float acc[8][8];
    #pragma unroll
    for (int i = 0; i < 8; i++)
        #pragma unroll
        for (int j = 0; j < 8; j++) acc[i][j] = 0.f;

    for (int k0 = 0; k0 < K; k0 += BK_) {
        // ---- load A tile ----
        if (LAYOUT == 0) {
            #pragma unroll
            for (int i = 0; i < 2; i++) {
                int f  = tid + i * 256;           // 0..511 float4s
                int k  = f >> 5;                  // 0..15
                int lv = (f & 31) << 2;           // 0..124
                float4 v = *(const float4*)(A + ((size_t)(b * K + k0 + k)) * Lv + l0 + lv);
                float sc = 1.f, tc = 0.f;
                if (sA) { sc = sA[b * K + k0 + k]; tc = tA[b * K + k0 + k]; }
                As[k][lv + 0] = v.x * sc + tc;
                As[k][lv + 1] = v.y * sc + tc;
                As[k][lv + 2] = v.z * sc + tc;
                As[k][lv + 3] = v.w * sc + tc;
            }
        } else {
            #pragma unroll
            for (int i = 0; i < 2; i++) {
                int f  = tid + i * 256;
                int m  = f >> 2;                  // 0..127
                int kq = (f & 3) << 2;            // 0,4,8,12
                float4 v = *(const float4*)(A + (size_t)(bm + m) * K + k0 + kq);
                float vv[4] = {v.x, v.y, v.z, v.w};
                #pragma unroll
                for (int j = 0; j < 4; j++) {
                    float val = vv[j];
                    if (sA) val = val * sA[b * K + k0 + kq + j] + tA[b * K + k0 + kq + j];
                    As[kq + j][m] = val;
                }
            }
        }
        // ---- load W tile ----
        #pragma unroll
        for (int i = 0; i < 2; i++) {
            int f = tid + i * 256;
            int k = f >> 5;
            int n = (f & 31) << 2;
            *(float4*)&Bs[k][n] = *(const float4*)(W + (size_t)(k0 + k) * N + bn + n);
        }
        __syncthreads();

        #pragma unroll
        for (int k = 0; k < BK_; k++) {
            float a[8], bb[8];
            #pragma unroll
            for (int i = 0; i < 8; i++) a[i] = As[k][ty * 8 + i];
            #pragma unroll
            for (int j = 0; j < 8; j++) bb[j] = Bs[k][tx * 8 + j];
            #pragma unroll
            for (int i = 0; i < 8; i++)
                #pragma unroll
                for (int j = 0; j < 8; j++) acc[i][j] += a[i] * bb[j];
        }
        __syncthreads();
    }

    // ---- epilogue ----
    #pragma unroll
    for (int i = 0; i < 8; i++) {
        size_t row = (size_t)(bm + ty * 8 + i);
        #pragma unroll
        for (int j = 0; j < 8; j += 4) {
            float4 r;
            float* pr = &r.x;
            #pragma unroll
            for (int jj = 0; jj < 4; jj++) {
                float val = acc[i][j + jj] + bias[bn + tx * 8 + j + jj];
                if (ACT == 1) val = val / (1.f + expf(-1.702f * val));
                pr[jj] = val;
            }
            *(float4*)(Y + row * N + bn + tx * 8 + j) = r;
        }
    }
}

// ---------------- KS=3 windowed attention --------------------------------
// one thread per (b, l, h)
__global__ void attn_kernel(const float* __restrict__ Q, const float* __restrict__ K,
                            const float* __restrict__ V, float* __restrict__ O)
{
    int idx = blockIdx.x * blockDim.x + threadIdx.x;  // B*L*H
    int h = idx & (Hv - 1);
    int l = (idx >> 3) & (Lv - 1);
    int b = idx >> 14;                                // / (H*L)

    size_t rowc = ((size_t)(b * Lv + l)) * Cv + h * Dhv;
    int lm = (l > 0)      ? l - 1 : l;
    int lp = (l < Lv - 1) ? l + 1 : l;
    size_t rowm = ((size_t)(b * Lv + lm)) * Cv + h * Dhv;
    size_t rowp = ((size_t)(b * Lv + lp)) * Cv + h * Dhv;

    const float4* q4 = (const float4*)(Q + rowc);
    const float4* ka = (const float4*)(K + rowm);
    const float4* kb = (const float4*)(K + rowc);
    const float4* kc = (const float4*)(K + rowp);

    float s0 = 0.f, s1 = 0.f, s2 = 0.f;
    #pragma unroll
    for (int i = 0; i < Dhv / 4; i++) {
        float4 q = q4[i], a = ka[i], c = kb[i], d = kc[i];
        s0 += q.x*a.x + q.y*a.y + q.z*a.z + q.w*a.w;
        s1 += q.x*c.x + q.y*c.y + q.z*c.z + q.w*c.w;
        s2 += q.x*d.x + q.y*d.y + q.z*d.z + q.w*d.w;
    }
    const float sc = 0.125f;                          // 1/sqrt(64)
    s0 = (l > 0)      ? s0 * sc : -1e9f;
    s1 = s1 * sc;
    s2 = (l < Lv - 1) ? s2 * sc : -1e9f;
    float mx = fmaxf(s1, fmaxf(s0, s2));
    float e0 = expf(s0 - mx), e1 = expf(s1 - mx), e2 = expf(s2 - mx);
    float inv = 1.f / (e0 + e1 + e2);
    e0 *= inv; e1 *= inv; e2 *= inv;

    const float4* va = (const float4*)(V + rowm);
    const float4* vb = (const float4*)(V + rowc);
    const float4* vc = (const float4*)(V + rowp);
    float4* o4 = (float4*)(O + rowc);
    #pragma unroll
    for (int i = 0; i < Dhv / 4; i++) {
        float4 a = va[i], c = vb[i], d = vc[i], r;
        r.x = e0*a.x + e1*c.x + e2*d.x;
        r.y = e0*a.y + e1*c.y + e2*d.y;
        r.z = e0*a.z + e1*c.z + e2*d.z;
        r.w = e0*a.w + e1*c.w + e2*d.w;
        o4[i] = r;
    }
}

// ---------------- final: out(B,C,L) = x + transpose(M(B*L,C)) ------------
__global__ void add_transpose_kernel(const float* __restrict__ x,
                                     const float* __restrict__ Mb,
                                     float* __restrict__ out)
{
    __shared__ float sm[32][33];
    int b  = blockIdx.z;
    int c0 = blockIdx.y * 32;
    int l0 = blockIdx.x * 32;
    int tx = threadIdx.x, ty = threadIdx.y;   // (32, 8)
    #pragma unroll
    for (int i = 0; i < 4; i++) {
        int l = l0 + ty + i * 8;
        sm[tx][ty + i * 8] = Mb[((size_t)(b * Lv + l)) * Cv + c0 + tx];
    }
    __syncthreads();
    #pragma unroll
    for (int i = 0; i < 4; i++) {
        int c = c0 + ty + i * 8;
        size_t off = ((size_t)(b * Cv + c)) * Lv + l0 + tx;
        out[off] = x[off] + sm[ty + i * 8][tx];
    }
}

// ---------------- launch ---------------------------------------------------
extern "C" void kernel_launch(void* const* d_in, const int* in_sizes, int n_in,
                              void* d_out, int out_size)
{
    const float* q   = (const float*)d_in[0];
    const float* x   = (const float*)d_in[1];
    const float* g1  = (const float*)d_in[2];
    const float* b1  = (const float*)d_in[3];
    const float* Wq  = (const float*)d_in[4];
    const float* bq  = (const float*)d_in[5];
    const float* Wk  = (const float*)d_in[6];
    const float* bk  = (const float*)d_in[7];
    const float* Wv  = (const float*)d_in[8];
    const float* bv  = (const float*)d_in[9];
    const float* Wo  = (const float*)d_in[10];
    const float* bo  = (const float*)d_in[11];
    const float* g2  = (const float*)d_in[12];
    const float* b2  = (const float*)d_in[13];
    const float* Wfc = (const float*)d_in[14];
    const float* bfc = (const float*)d_in[15];
    const float* Wpr = (const float*)d_in[16];
    const float* bpr = (const float*)d_in[17];
    float* out = (float*)d_out;

    float *Qb, *Kb, *Vb, *Ob, *Yb, *Ub, *Mb, *S1, *T1, *S2, *T2;
    cudaGetSymbolAddress((void**)&Qb, g_Q);
    cudaGetSymbolAddress((void**)&Kb, g_K);
    cudaGetSymbolAddress((void**)&Vb, g_V);
    cudaGetSymbolAddress((void**)&Ob, g_O);
    cudaGetSymbolAddress((void**)&Yb, g_Y);
    cudaGetSymbolAddress((void**)&Ub, g_U);
    cudaGetSymbolAddress((void**)&Mb, g_M);
    cudaGetSymbolAddress((void**)&S1, g_S1);
    cudaGetSymbolAddress((void**)&T1, g_T1);
    cudaGetSymbolAddress((void**)&S2, g_S2);
    cudaGetSymbolAddress((void**)&T2, g_T2);

    const int Mrows = Bv * Lv;                        // 32768

    // 1) instance-norm(x) stats -> per-(b,c) affine
    rowstats_kernel<<<Bv * Cv, 256>>>(x, g1, b1, S1, T1);

    // 2) Q/K/V projections (norm fused into K/V A-load)
    dim3 g512(512 / BN_, Mrows / BM_);
    gemm_kernel<0, 0><<<g512, 256>>>(q, Wq, bq, nullptr, nullptr, Qb, 512, 512);
    gemm_kernel<0, 0><<<g512, 256>>>(x, Wk, bk, S1, T1, Kb, 512, 512);
    gemm_kernel<0, 0><<<g512, 256>>>(x, Wv, bv, S1, T1, Vb, 512, 512);

    // 3) windowed attention
    attn_kernel<<<(Bv * Lv * Hv) / 256, 256>>>(Qb, Kb, Vb, Ob);

    // 4) output projection
    gemm_kernel<1, 0><<<g512, 256>>>(Ob, Wo, bo, nullptr, nullptr, Yb, 512, 512);

    // 5) instance-norm(y over l) stats
    colstats_kernel<<<dim3(Cv / 32, Bv), 256>>>(Yb, g2, b2, S2, T2);

    // 6) MLP: fc (+QuickGELU), proj
    dim3 g1024(1024 / BN_, Mrows / BM_);
    gemm_kernel<1, 1><<<g1024, 256>>>(Yb, Wfc, bfc, S2, T2, Ub, 1024, 512);
    gemm_kernel<1, 0><<<g512, 256>>>(Ub, Wpr, bpr, nullptr, nullptr, Mb, 512, 1024);

    // 7) residual + transpose back to (B,C,L)
    add_transpose_kernel<<<dim3(Lv / 32, Cv / 32, Bv), dim3(32, 8)>>>(x, Mb, out);
}

// round 4
// speedup vs baseline: 2.4637x; 2.4637x over previous
#include <cuda_runtime.h>
#include <math.h>
#include <stdint.h>

// ---------------- problem constants ----------------
constexpr int Bv  = 16;
constexpr int Cv  = 512;
constexpr int Lv  = 2048;
constexpr int Hv  = 8;
constexpr int Dhv = 64;

// ---------------- mma GEMM config ----------------
constexpr int BM  = 128;
constexpr int BN  = 128;
constexpr int BKK = 32;
constexpr int A_STRIDE = BKK + 4;           // 36 floats per A row
constexpr int B_STRIDE = BN + 8;            // 136 floats per B row
constexpr int A_FLOATS = BM * A_STRIDE;     // 4608
constexpr int B_FLOATS = BKK * B_STRIDE;    // 4352
constexpr int STAGE_FLOATS = A_FLOATS + B_FLOATS;   // 8960
constexpr int SMEM_GEMM = 2 * STAGE_FLOATS * 4;     // 71680 bytes

// ---------------- scratch ----------------
__device__ float g_QT[16777216];   // q transposed (B*L, C), tf32-rounded
__device__ float g_XT[16777216];   // normed x transposed (B*L, C), tf32-rounded
__device__ float g_Q[16777216];
__device__ float g_K[16777216];
__device__ float g_V[16777216];
__device__ float g_O[16777216];    // attention out (tf32-rounded)
__device__ float g_Y[16777216];
__device__ float g_U[33554432];    // fc out (tf32-rounded)
__device__ float g_WT[2097152];    // tf32-rounded weights, same [K,N] layout
__device__ float g_S1[Bv*Cv], g_T1[Bv*Cv];
__device__ float g_S2[Bv*Cv], g_T2[Bv*Cv];

constexpr int WQ_OFF  = 0;
constexpr int WK_OFF  = 262144;
constexpr int WV_OFF  = 524288;
constexpr int WO_OFF  = 786432;
constexpr int WFC_OFF = 1048576;
constexpr int WPR_OFF = 1572864;

// ---------------- helpers ----------------
__device__ __forceinline__ uint32_t smem_u32(const void* p) {
    uint32_t a;
    asm("{ .reg .u64 t; cvta.to.shared.u64 t, %1; cvt.u32.u64 %0, t; }" : "=r"(a) : "l"(p));
    return a;
}
__device__ __forceinline__ float tf32r(float v) {
    uint32_t u;
    asm("cvt.rna.tf32.f32 %0, %1;" : "=r"(u) : "f"(v));
    return __uint_as_float(u);
}
__device__ __forceinline__ void cpa16(uint32_t dst, const void* src) {
    asm volatile("cp.async.cg.shared.global [%0], [%1], 16;" :: "r"(dst), "l"(src) : "memory");
}
template<int NW>
__device__ __forceinline__ void cpwait() {
    asm volatile("cp.async.wait_group %0;" :: "n"(NW) : "memory");
}

#define MMA8(d, a, b0, b1)                                                  \
    asm volatile("mma.sync.aligned.m16n8k8.row.col.f32.tf32.tf32.f32 "      \
        "{%0,%1,%2,%3}, {%4,%5,%6,%7}, {%8,%9}, {%0,%1,%2,%3};"             \
        : "+f"((d)[0]), "+f"((d)[1]), "+f"((d)[2]), "+f"((d)[3])            \
        : "r"((a)[0]), "r"((a)[1]), "r"((a)[2]), "r"((a)[3]),               \
          "r"(b0), "r"(b1))

// ---------------- instance-norm stats over rows of x (B,C,L) -------------
__global__ void rowstats_kernel(const float* __restrict__ x,
                                const float* __restrict__ gamma,
                                const float* __restrict__ beta,
                                float* __restrict__ s, float* __restrict__ t)
{
    int row = blockIdx.x;                  // b*C + c
    const float4* p = (const float4*)(x + (size_t)row * Lv);
    float sum = 0.f, sq = 0.f;
    for (int i = threadIdx.x; i < Lv / 4; i += blockDim.x) {
        float4 v = p[i];
        sum += v.x + v.y + v.z + v.w;
        sq  += v.x*v.x + v.y*v.y + v.z*v.z + v.w*v.w;
    }
    __shared__ float ssum[8], ssq[8];
    for (int o = 16; o; o >>= 1) {
        sum += __shfl_down_sync(0xffffffffu, sum, o);
        sq  += __shfl_down_sync(0xffffffffu, sq,  o);
    }
    int wid = threadIdx.x >> 5, lane = threadIdx.x & 31;
    if (lane == 0) { ssum[wid] = sum; ssq[wid] = sq; }
    __syncthreads();
    if (wid == 0) {
        sum = lane < (blockDim.x >> 5) ? ssum[lane] : 0.f;
        sq  = lane < (blockDim.x >> 5) ? ssq[lane]  : 0.f;
        for (int o = 4; o; o >>= 1) {
            sum += __shfl_down_sync(0xffffffffu, sum, o);
            sq  += __shfl_down_sync(0xffffffffu, sq,  o);
        }
        if (lane == 0) {
            float mean = sum / (float)Lv;
            float var  = sq / (float)Lv - mean * mean;
            float rstd = rsqrtf(var + 1e-5f);
            int c = row % Cv;
            float sv = gamma[c] * rstd;
            s[row] = sv;
            t[row] = beta[c] - mean * sv;
        }
    }
}

// ---------------- instance-norm stats over columns of y (B*L, C) ---------
__global__ void colstats_kernel(const float* __restrict__ y,
                                const float* __restrict__ gamma,
                                const float* __restrict__ beta,
                                float* __restrict__ s, float* __restrict__ t)
{
    int b  = blockIdx.y;
    int ci = threadIdx.x & 31;
    int lj = threadIdx.x >> 5;
    int c  = blockIdx.x * 32 + ci;
    const float* base = y + (size_t)b * Lv * Cv + c;
    float sum = 0.f, sq = 0.f;
    for (int l = lj; l < Lv; l += 8) {
        float v = base[(size_t)l * Cv];
        sum += v; sq += v * v;
    }
    __shared__ float S[8][32], Q[8][32];
    S[lj][ci] = sum; Q[lj][ci] = sq;
    __syncthreads();
    if (lj == 0) {
        #pragma unroll
        for (int j = 1; j < 8; j++) { sum += S[j][ci]; sq += Q[j][ci]; }
        float mean = sum / (float)Lv;
        float var  = sq / (float)Lv - mean * mean;
        float rstd = rsqrtf(var + 1e-5f);
        float sv = gamma[c] * rstd;
        s[b * Cv + c] = sv;
        t[b * Cv + c] = beta[c] - mean * sv;
    }
}

// ---------------- normapply: Y = tf32(Y*s + t) (per (b,c)) ----------------
__global__ void normapply_kernel(float* __restrict__ Y,
                                 const float* __restrict__ s,
                                 const float* __restrict__ t)
{
    int i = blockIdx.x * blockDim.x + threadIdx.x;   // float4 index
    float4 v = ((float4*)Y)[i];
    int e = i * 4;
    int c = e & (Cv - 1);
    int b = e >> 20;                                  // / (Lv*Cv)
    const float* sb = s + b * Cv + c;
    const float* tb = t + b * Cv + c;
    v.x = tf32r(v.x * sb[0] + tb[0]);
    v.y = tf32r(v.y * sb[1] + tb[1]);
    v.z = tf32r(v.z * sb[2] + tb[2]);
    v.w = tf32r(v.w * sb[3] + tb[3]);
    ((float4*)Y)[i] = v;
}

// ---------------- transpose (B,C,L) -> (B*L,C), optional affine, tf32 -----
__global__ void transpose_in(const float* __restrict__ src,
                             const float* __restrict__ s,
                             const float* __restrict__ t,
                             float* __restrict__ dst)
{
    __shared__ float sm[32][33];
    int b  = blockIdx.z;
    int c0 = blockIdx.y * 32;
    int l0 = blockIdx.x * 32;
    int tx = threadIdx.x, ty = threadIdx.y;
    #pragma unroll
    for (int i = 0; i < 4; i++) {
        int c = c0 + ty + i * 8;
        float v = src[((size_t)(b * Cv + c)) * Lv + l0 + tx];
        if (s) v = v * s[b * Cv + c] + t[b * Cv + c];
        sm[ty + i * 8][tx] = v;
    }
    __syncthreads();
    #pragma unroll
    for (int i = 0; i < 4; i++) {
        int l = l0 + ty + i * 8;
        dst[((size_t)(b * Lv + l)) * Cv + c0 + tx] = tf32r(sm[tx][ty + i * 8]);
    }
}

// ---------------- round-copy weights to tf32 (same layout) ----------------
__global__ void roundcopy_kernel(const float* __restrict__ src, float* __restrict__ dst)
{
    int i = blockIdx.x * blockDim.x + threadIdx.x;
    float4 v = ((const float4*)src)[i];
    v.x = tf32r(v.x); v.y = tf32r(v.y); v.z = tf32r(v.z); v.w = tf32r(v.w);
    ((float4*)dst)[i] = v;
}

// ---------------- tf32 mma.sync GEMM --------------------------------------
// Y[M,N] = act( A[M,K] @ W[K,N] + bias )  (A row-major, W row-major)
// ACT 0: none   ACT 1: QuickGELU + tf32 round   ACT 2: residual + transpose out
// Block 256 thr = 8 warps (4m x 2n); warp tile 32x64; mma m16n8k8 tf32.
template<int ACT>
__global__ void __launch_bounds__(256)
mma_gemm(const float* __restrict__ A, const float* __restrict__ W,
         const float* __restrict__ bias, float* __restrict__ Y,
         int K, int N, const float* __restrict__ xres)
{
    extern __shared__ float sm[];
    const int tid  = threadIdx.x;
    const int bm   = blockIdx.y * BM;
    const int bn   = blockIdx.x * BN;
    const int lane = tid & 31, warp = tid >> 5;
    const int wm   = warp & 3, wn = warp >> 2;
    const int r    = lane >> 2, t = lane & 3;
    const uint32_t sbase = smem_u32(sm);
    const int nch = K / BKK;

    float acc[2][8][4];
    #pragma unroll
    for (int mt = 0; mt < 2; mt++)
        #pragma unroll
        for (int nt = 0; nt < 8; nt++)
            #pragma unroll
            for (int j = 0; j < 4; j++) acc[mt][nt][j] = 0.f;

    auto issue = [&](int c) {
        uint32_t as = sbase + (uint32_t)((c & 1) * STAGE_FLOATS * 4);
        uint32_t bs = as + A_FLOATS * 4;
        const float* ga = A + (size_t)bm * K + c * BKK;
        #pragma unroll
        for (int i = 0; i < 4; i++) {
            int id = tid + i * 256;
            int m = id >> 3, q = id & 7;
            cpa16(as + (uint32_t)((m * A_STRIDE + q * 4) * 4),
                  ga + (size_t)m * K + q * 4);
        }
        const float* gb = W + (size_t)(c * BKK) * N + bn;
        #pragma unroll
        for (int i = 0; i < 4; i++) {
            int id = tid + i * 256;
            int k = id >> 5, q = id & 31;
            cpa16(bs + (uint32_t)((k * B_STRIDE + q * 4) * 4),
                  gb + (size_t)k * N + q * 4);
        }
        asm volatile("cp.async.commit_group;" ::: "memory");
    };

    issue(0);
    for (int c = 0; c < nch; c++) {
        if (c + 1 < nch) { issue(c + 1); cpwait<1>(); }
        else             { cpwait<0>(); }
        __syncthreads();
        const float* As = sm + (c & 1) * STAGE_FLOATS;
        const float* Bs = As + A_FLOATS;
        #pragma unroll
        for (int ks = 0; ks < 4; ks++) {
            const int kb = ks * 8;
            uint32_t a[2][4];
            #pragma unroll
            for (int mt = 0; mt < 2; mt++) {
                int m = wm * 32 + mt * 16;
                a[mt][0] = __float_as_uint(As[(m + r)     * A_STRIDE + kb + t]);
                a[mt][1] = __float_as_uint(As[(m + r + 8) * A_STRIDE + kb + t]);
                a[mt][2] = __float_as_uint(As[(m + r)     * A_STRIDE + kb + t + 4]);
                a[mt][3] = __float_as_uint(As[(m + r + 8) * A_STRIDE + kb + t + 4]);
            }
            #pragma unroll
            for (int nt = 0; nt < 8; nt++) {
                int n = wn * 64 + nt * 8 + r;
                uint32_t b0 = __float_as_uint(Bs[(kb + t)     * B_STRIDE + n]);
                uint32_t b1 = __float_as_uint(Bs[(kb + t + 4) * B_STRIDE + n]);
                MMA8(acc[0][nt], a[0], b0, b1);
                MMA8(acc[1][nt], a[1], b0, b1);
            }
        }
        __syncthreads();
    }

    // ---- epilogue ----
    #pragma unroll
    for (int mt = 0; mt < 2; mt++) {
        #pragma unroll
        for (int half = 0; half < 2; half++) {
            int row = bm + wm * 32 + mt * 16 + r + half * 8;
            int bnum = row >> 11;            // / Lv
            int l    = row & (Lv - 1);
            #pragma unroll
            for (int nt = 0; nt < 8; nt++) {
                int col = bn + wn * 64 + nt * 8 + 2 * t;
                float v0 = acc[mt][nt][half * 2 + 0] + bias[col];
                float v1 = acc[mt][nt][half * 2 + 1] + bias[col + 1];
                if (ACT == 1) {
                    v0 = tf32r(v0 / (1.f + __expf(-1.702f * v0)));
                    v1 = tf32r(v1 / (1.f + __expf(-1.702f * v1)));
                }
                if (ACT == 2) {
                    size_t o0 = ((size_t)(bnum * Cv + col)) * Lv + l;
                    Y[o0]      = xres[o0]      + v0;
                    Y[o0 + Lv] = xres[o0 + Lv] + v1;
                } else {
                    float2 w; w.x = v0; w.y = v1;
                    *(float2*)(Y + (size_t)row * N + col) = w;
                }
            }
        }
    }
}

// ---------------- KS=3 windowed attention --------------------------------
__global__ void attn_kernel(const float* __restrict__ Q, const float* __restrict__ K,
                            const float* __restrict__ V, float* __restrict__ O)
{
    int idx = blockIdx.x * blockDim.x + threadIdx.x;
    int h = idx & (Hv - 1);
    int l = (idx >> 3) & (Lv - 1);
    int b = idx >> 14;

    size_t rowc = ((size_t)(b * Lv + l)) * Cv + h * Dhv;
    int lm = (l > 0)      ? l - 1 : l;
    int lp = (l < Lv - 1) ? l + 1 : l;
    size_t rowm = ((size_t)(b * Lv + lm)) * Cv + h * Dhv;
    size_t rowp = ((size_t)(b * Lv + lp)) * Cv + h * Dhv;

    const float4* q4 = (const float4*)(Q + rowc);
    const float4* ka = (const float4*)(K + rowm);
    const float4* kb = (const float4*)(K + rowc);
    const float4* kc = (const float4*)(K + rowp);

    float s0 = 0.f, s1 = 0.f, s2 = 0.f;
    #pragma unroll
    for (int i = 0; i < Dhv / 4; i++) {
        float4 q = q4[i], a = ka[i], c = kb[i], d = kc[i];
        s0 += q.x*a.x + q.y*a.y + q.z*a.z + q.w*a.w;
        s1 += q.x*c.x + q.y*c.y + q.z*c.z + q.w*c.w;
        s2 += q.x*d.x + q.y*d.y + q.z*d.z + q.w*d.w;
    }
    const float sc = 0.125f;
    s0 = (l > 0)      ? s0 * sc : -1e9f;
    s1 = s1 * sc;
    s2 = (l < Lv - 1) ? s2 * sc : -1e9f;
    float mx = fmaxf(s1, fmaxf(s0, s2));
    float e0 = expf(s0 - mx), e1 = expf(s1 - mx), e2 = expf(s2 - mx);
    float inv = 1.f / (e0 + e1 + e2);
    e0 *= inv; e1 *= inv; e2 *= inv;

    const float4* va = (const float4*)(V + rowm);
    const float4* vb = (const float4*)(V + rowc);
    const float4* vc = (const float4*)(V + rowp);
    float4* o4 = (float4*)(O + rowc);
    #pragma unroll
    for (int i = 0; i < Dhv / 4; i++) {
        float4 a = va[i], c = vb[i], d = vc[i], r;
        r.x = tf32r(e0*a.x + e1*c.x + e2*d.x);
        r.y = tf32r(e0*a.y + e1*c.y + e2*d.y);
        r.z = tf32r(e0*a.z + e1*c.z + e2*d.z);
        r.w = tf32r(e0*a.w + e1*c.w + e2*d.w);
        o4[i] = r;
    }
}

// ---------------- launch ---------------------------------------------------
extern "C" void kernel_launch(void* const* d_in, const int* in_sizes, int n_in,
                              void* d_out, int out_size)
{
    const float* q   = (const float*)d_in[0];
    const float* x   = (const float*)d_in[1];
    const float* g1  = (const float*)d_in[2];
    const float* b1  = (const float*)d_in[3];
    const float* Wq  = (const float*)d_in[4];
    const float* bq  = (const float*)d_in[5];
    const float* Wk  = (const float*)d_in[6];
    const float* bk  = (const float*)d_in[7];
    const float* Wv  = (const float*)d_in[8];
    const float* bv  = (const float*)d_in[9];
    const float* Wo  = (const float*)d_in[10];
    const float* bo  = (const float*)d_in[11];
    const float* g2  = (const float*)d_in[12];
    const float* b2  = (const float*)d_in[13];
    const float* Wfc = (const float*)d_in[14];
    const float* bfc = (const float*)d_in[15];
    const float* Wpr = (const float*)d_in[16];
    const float* bpr = (const float*)d_in[17];
    float* out = (float*)d_out;

    float *QT, *XT, *Qb, *Kb, *Vb, *Ob, *Yb, *Ub, *WT, *S1, *T1, *S2, *T2;
    cudaGetSymbolAddress((void**)&QT, g_QT);
    cudaGetSymbolAddress((void**)&XT, g_XT);
    cudaGetSymbolAddress((void**)&Qb, g_Q);
    cudaGetSymbolAddress((void**)&Kb, g_K);
    cudaGetSymbolAddress((void**)&Vb, g_V);
    cudaGetSymbolAddress((void**)&Ob, g_O);
    cudaGetSymbolAddress((void**)&Yb, g_Y);
    cudaGetSymbolAddress((void**)&Ub, g_U);
    cudaGetSymbolAddress((void**)&WT, g_WT);
    cudaGetSymbolAddress((void**)&S1, g_S1);
    cudaGetSymbolAddress((void**)&T1, g_T1);
    cudaGetSymbolAddress((void**)&S2, g_S2);
    cudaGetSymbolAddress((void**)&T2, g_T2);

    cudaFuncSetAttribute(mma_gemm<0>, cudaFuncAttributeMaxDynamicSharedMemorySize, SMEM_GEMM);
    cudaFuncSetAttribute(mma_gemm<1>, cudaFuncAttributeMaxDynamicSharedMemorySize, SMEM_GEMM);
    cudaFuncSetAttribute(mma_gemm<2>, cudaFuncAttributeMaxDynamicSharedMemorySize, SMEM_GEMM);

    // 1) norm1 stats + staging transposes (norm fused, tf32-rounded)
    rowstats_kernel<<<Bv * Cv, 256>>>(x, g1, b1, S1, T1);
    dim3 tin_g(Lv / 32, Cv / 32, Bv), tin_b(32, 8);
    transpose_in<<<tin_g, tin_b>>>(q, nullptr, nullptr, QT);
    transpose_in<<<tin_g, tin_b>>>(x, S1, T1, XT);

    // 2) round weights to tf32 (same [K,N] layout)
    roundcopy_kernel<<<(512 * 512 / 4) / 256, 256>>>(Wq,  WT + WQ_OFF);
    roundcopy_kernel<<<(512 * 512 / 4) / 256, 256>>>(Wk,  WT + WK_OFF);
    roundcopy_kernel<<<(512 * 512 / 4) / 256, 256>>>(Wv,  WT + WV_OFF);
    roundcopy_kernel<<<(512 * 512 / 4) / 256, 256>>>(Wo,  WT + WO_OFF);
    roundcopy_kernel<<<(512 * 1024 / 4) / 256, 256>>>(Wfc, WT + WFC_OFF);
    roundcopy_kernel<<<(1024 * 512 / 4) / 256, 256>>>(Wpr, WT + WPR_OFF);

    const int Mt = (Bv * Lv) / BM;   // 256
    dim3 g512(512 / BN, Mt), g1024(1024 / BN, Mt);

    // 3) Q/K/V projections (tensor cores, tf32)
    mma_gemm<0><<<g512, 256, SMEM_GEMM>>>(QT, WT + WQ_OFF, bq, Qb, 512, 512, nullptr);
    mma_gemm<0><<<g512, 256, SMEM_GEMM>>>(XT, WT + WK_OFF, bk, Kb, 512, 512, nullptr);
    mma_gemm<0><<<g512, 256, SMEM_GEMM>>>(XT, WT + WV_OFF, bv, Vb, 512, 512, nullptr);

    // 4) windowed attention (output tf32-rounded)
    attn_kernel<<<(Bv * Lv * Hv) / 256, 256>>>(Qb, Kb, Vb, Ob);

    // 5) output projection
    mma_gemm<0><<<g512, 256, SMEM_GEMM>>>(Ob, WT + WO_OFF, bo, Yb, 512, 512, nullptr);

    // 6) norm2 stats + apply in place (rounds to tf32)
    colstats_kernel<<<dim3(Cv / 32, Bv), 256>>>(Yb, g2, b2, S2, T2);
    normapply_kernel<<<(Bv * Lv * Cv / 4) / 256, 256>>>(Yb, S2, T2);

    // 7) MLP: fc + QuickGELU (rounds), then proj with fused residual+transpose
    mma_gemm<1><<<g1024, 256, SMEM_GEMM>>>(Yb, WT + WFC_OFF, bfc, Ub, 512, 1024, nullptr);
    mma_gemm<2><<<g512, 256, SMEM_GEMM>>>(Ub, WT + WPR_OFF, bpr, out, 1024, 512, x);
}

// round 5
// speedup vs baseline: 4.4803x; 1.8185x over previous
#include <cuda_runtime.h>
#include <cuda_fp16.h>
#include <math.h>
#include <stdint.h>

// ---------------- problem constants ----------------
constexpr int Bv  = 16;
constexpr int Cv  = 512;
constexpr int Lv  = 2048;
constexpr int Hv  = 8;
constexpr int Dhv = 64;

// ---------------- fp16 mma GEMM config ----------------
constexpr int BM  = 128;
constexpr int BN  = 128;
constexpr int BKK = 32;
constexpr int A_STRIDE = 40;                 // halfs per A row (80B, conflict-free)
constexpr int B_STRIDE = 136;                // halfs per B row (272B, conflict-free)
constexpr int A_HALFS  = BM * A_STRIDE;      // 5120
constexpr int B_HALFS  = BKK * B_STRIDE;     // 4352
constexpr int STAGE_BYTES = (A_HALFS + B_HALFS) * 2;   // 18944
constexpr int STAGES = 4;
constexpr int SMEM_GEMM = STAGES * STAGE_BYTES;        // 75776

// ---------------- scratch (half precision staging) ----------------
__device__ __half g_QT[16777216];
__device__ __half g_XT[16777216];
__device__ __half g_Q[16777216];
__device__ __half g_K[16777216];
__device__ __half g_V[16777216];
__device__ __half g_O[16777216];
__device__ __half g_Y[16777216];
__device__ __half g_U[33554432];
__device__ __half g_WT[2097152];
__device__ float  g_S1[Bv*Cv], g_T1[Bv*Cv];
__device__ float  g_S2[Bv*Cv], g_T2[Bv*Cv];

constexpr int WQ_OFF  = 0;
constexpr int WK_OFF  = 262144;
constexpr int WV_OFF  = 524288;
constexpr int WO_OFF  = 786432;
constexpr int WFC_OFF = 1048576;
constexpr int WPR_OFF = 1572864;

// ---------------- helpers ----------------
__device__ __forceinline__ uint32_t smem_u32(const void* p) {
    uint32_t a;
    asm("{ .reg .u64 t; cvta.to.shared.u64 t, %1; cvt.u32.u64 %0, t; }" : "=r"(a) : "l"(p));
    return a;
}
__device__ __forceinline__ void cpa16(uint32_t dst, const void* src) {
    asm volatile("cp.async.cg.shared.global [%0], [%1], 16;" :: "r"(dst), "l"(src) : "memory");
}
template<int NW>
__device__ __forceinline__ void cpwait() {
    asm volatile("cp.async.wait_group %0;" :: "n"(NW) : "memory");
}

#define LDSM4(r0, r1, r2, r3, addr)                                          \
    asm volatile("ldmatrix.sync.aligned.m8n8.x4.shared.b16 {%0,%1,%2,%3}, [%4];" \
        : "=r"(r0), "=r"(r1), "=r"(r2), "=r"(r3) : "r"(addr))

#define LDSM4T(r0, r1, r2, r3, addr)                                         \
    asm volatile("ldmatrix.sync.aligned.m8n8.x4.trans.shared.b16 {%0,%1,%2,%3}, [%4];" \
        : "=r"(r0), "=r"(r1), "=r"(r2), "=r"(r3) : "r"(addr))

#define MMA16(d, a, b0, b1)                                                  \
    asm volatile("mma.sync.aligned.m16n8k16.row.col.f32.f16.f16.f32 "        \
        "{%0,%1,%2,%3}, {%4,%5,%6,%7}, {%8,%9}, {%0,%1,%2,%3};"              \
        : "+f"((d)[0]), "+f"((d)[1]), "+f"((d)[2]), "+f"((d)[3])             \
        : "r"((a)[0]), "r"((a)[1]), "r"((a)[2]), "r"((a)[3]),                \
          "r"(b0), "r"(b1))

// ---------------- instance-norm stats over rows of x (B,C,L) -------------
__global__ void rowstats_kernel(const float* __restrict__ x,
                                const float* __restrict__ gamma,
                                const float* __restrict__ beta,
                                float* __restrict__ s, float* __restrict__ t)
{
    int row = blockIdx.x;
    const float4* p = (const float4*)(x + (size_t)row * Lv);
    float sum = 0.f, sq = 0.f;
    for (int i = threadIdx.x; i < Lv / 4; i += blockDim.x) {
        float4 v = p[i];
        sum += v.x + v.y + v.z + v.w;
        sq  += v.x*v.x + v.y*v.y + v.z*v.z + v.w*v.w;
    }
    __shared__ float ssum[8], ssq[8];
    for (int o = 16; o; o >>= 1) {
        sum += __shfl_down_sync(0xffffffffu, sum, o);
        sq  += __shfl_down_sync(0xffffffffu, sq,  o);
    }
    int wid = threadIdx.x >> 5, lane = threadIdx.x & 31;
    if (lane == 0) { ssum[wid] = sum; ssq[wid] = sq; }
    __syncthreads();
    if (wid == 0) {
        sum = lane < (blockDim.x >> 5) ? ssum[lane] : 0.f;
        sq  = lane < (blockDim.x >> 5) ? ssq[lane]  : 0.f;
        for (int o = 4; o; o >>= 1) {
            sum += __shfl_down_sync(0xffffffffu, sum, o);
            sq  += __shfl_down_sync(0xffffffffu, sq,  o);
        }
        if (lane == 0) {
            float mean = sum / (float)Lv;
            float var  = sq / (float)Lv - mean * mean;
            float rstd = rsqrtf(var + 1e-5f);
            int c = row % Cv;
            float sv = gamma[c] * rstd;
            s[row] = sv;
            t[row] = beta[c] - mean * sv;
        }
    }
}

// ---------------- instance-norm stats over columns of y (B*L, C) half ----
__global__ void colstats_kernel(const __half* __restrict__ y,
                                const float* __restrict__ gamma,
                                const float* __restrict__ beta,
                                float* __restrict__ s, float* __restrict__ t)
{
    int b  = blockIdx.y;
    int ci = threadIdx.x & 31;
    int lj = threadIdx.x >> 5;
    int c  = blockIdx.x * 32 + ci;
    const __half* base = y + (size_t)b * Lv * Cv + c;
    float sum = 0.f, sq = 0.f;
    for (int l = lj; l < Lv; l += 8) {
        float v = __half2float(base[(size_t)l * Cv]);
        sum += v; sq += v * v;
    }
    __shared__ float S[8][32], Q[8][32];
    S[lj][ci] = sum; Q[lj][ci] = sq;
    __syncthreads();
    if (lj == 0) {
        #pragma unroll
        for (int j = 1; j < 8; j++) { sum += S[j][ci]; sq += Q[j][ci]; }
        float mean = sum / (float)Lv;
        float var  = sq / (float)Lv - mean * mean;
        float rstd = rsqrtf(var + 1e-5f);
        float sv = gamma[c] * rstd;
        s[b * Cv + c] = sv;
        t[b * Cv + c] = beta[c] - mean * sv;
    }
}

// ---------------- normapply: Y = half(Y*s + t) per (b,c), in place --------
__global__ void normapply_kernel(__half* __restrict__ Y,
                                 const float* __restrict__ s,
                                 const float* __restrict__ t)
{
    int i = blockIdx.x * blockDim.x + threadIdx.x;   // half2 index
    __half2 hv = ((__half2*)Y)[i];
    float2 v = __half22float2(hv);
    int e = i * 2;
    int c = e & (Cv - 1);
    int b = e >> 20;
    const float* sb = s + b * Cv + c;
    const float* tb = t + b * Cv + c;
    v.x = v.x * sb[0] + tb[0];
    v.y = v.y * sb[1] + tb[1];
    ((__half2*)Y)[i] = __floats2half2_rn(v.x, v.y);
}

// ---------------- transpose (B,C,L) fp32 -> (B*L,C) fp16, opt affine ------
__global__ void transpose_in(const float* __restrict__ src,
                             const float* __restrict__ s,
                             const float* __restrict__ t,
                             __half* __restrict__ dst)
{
    __shared__ float sm[32][33];
    int b  = blockIdx.z;
    int c0 = blockIdx.y * 32;
    int l0 = blockIdx.x * 32;
    int tx = threadIdx.x, ty = threadIdx.y;
    #pragma unroll
    for (int i = 0; i < 4; i++) {
        int c = c0 + ty + i * 8;
        float v = src[((size_t)(b * Cv + c)) * Lv + l0 + tx];
        if (s) v = v * s[b * Cv + c] + t[b * Cv + c];
        sm[ty + i * 8][tx] = v;
    }
    __syncthreads();
    #pragma unroll
    for (int i = 0; i < 4; i++) {
        int l = l0 + ty + i * 8;
        dst[((size_t)(b * Lv + l)) * Cv + c0 + tx] = __float2half(sm[tx][ty + i * 8]);
    }
}

// ---------------- weights fp32 -> fp16 (same [K,N] layout) ----------------
__global__ void w2h_kernel(const float* __restrict__ src, __half* __restrict__ dst)
{
    int i = blockIdx.x * blockDim.x + threadIdx.x;   // float4 index
    float4 v = ((const float4*)src)[i];
    __half2 h0 = __floats2half2_rn(v.x, v.y);
    __half2 h1 = __floats2half2_rn(v.z, v.w);
    ((__half2*)dst)[i * 2]     = h0;
    ((__half2*)dst)[i * 2 + 1] = h1;
}

// ---------------- fp16 mma.sync GEMM --------------------------------------
// Y = act( A[M,K]h @ W[K,N]h + bias_f )
// ACT 0: none (half out)  ACT 1: QuickGELU (half out)  ACT 2: residual+transpose (f32 out)
// 256 thr = 8 warps (4m x 2n); warp tile 32x64; mma m16n8k16 f16.f32.
template<int ACT>
__global__ void __launch_bounds__(256)
mma_gemm(const __half* __restrict__ A, const __half* __restrict__ W,
         const float* __restrict__ bias, void* __restrict__ Yv,
         int K, int N, const float* __restrict__ xres)
{
    extern __shared__ __align__(16) char smem[];
    const int tid  = threadIdx.x;
    const int bm   = blockIdx.y * BM;
    const int bn   = blockIdx.x * BN;
    const int lane = tid & 31, warp = tid >> 5;
    const int wm   = warp & 3, wn = warp >> 2;
    const int r    = lane >> 2, t = lane & 3;
    const uint32_t sbase = smem_u32(smem);
    const int nch = K / BKK;

    float acc[2][8][4];
    #pragma unroll
    for (int mt = 0; mt < 2; mt++)
        #pragma unroll
        for (int nt = 0; nt < 8; nt++)
            #pragma unroll
            for (int j = 0; j < 4; j++) acc[mt][nt][j] = 0.f;

    auto issue = [&](int c) {
        uint32_t as = sbase + (uint32_t)((c % STAGES) * STAGE_BYTES);
        uint32_t bs = as + A_HALFS * 2;
        const __half* ga = A + (size_t)bm * K + c * BKK;
        #pragma unroll
        for (int i = 0; i < 2; i++) {
            int id = tid + i * 256;
            int m = id >> 2, q = id & 3;                    // 4 x 16B per row
            cpa16(as + (uint32_t)(m * 80 + q * 16),
                  ga + (size_t)m * K + q * 8);
        }
        const __half* gb = W + (size_t)(c * BKK) * N + bn;
        #pragma unroll
        for (int i = 0; i < 2; i++) {
            int id = tid + i * 256;
            int k = id >> 4, q = id & 15;                   // 16 x 16B per row
            cpa16(bs + (uint32_t)(k * 272 + q * 16),
                  gb + (size_t)k * N + q * 8);
        }
        asm volatile("cp.async.commit_group;" ::: "memory");
    };

    issue(0); issue(1); issue(2);

    // ldmatrix lane addressing (shared by A and B patterns)
    const int l15 = lane & 15;
    const int hi8 = (lane >> 4) << 3;   // 0 or 8

    for (int c = 0; c < nch; c++) {
        if (c + 2 < nch)      cpwait<2>();
        else if (c + 1 < nch) cpwait<1>();
        else                  cpwait<0>();
        __syncthreads();
        if (c + 3 < nch) issue(c + 3);

        uint32_t as = sbase + (uint32_t)((c % STAGES) * STAGE_BYTES);
        uint32_t bs = as + A_HALFS * 2;

        #pragma unroll
        for (int ks = 0; ks < 2; ks++) {
            uint32_t a[2][4];
            #pragma unroll
            for (int mt = 0; mt < 2; mt++) {
                uint32_t addr = as + (uint32_t)(
                    (wm * 32 + mt * 16 + l15) * 80 + ks * 32 + hi8 * 2);
                LDSM4(a[mt][0], a[mt][1], a[mt][2], a[mt][3], addr);
            }
            #pragma unroll
            for (int nt4 = 0; nt4 < 4; nt4++) {
                uint32_t b[4];
                uint32_t addr = bs + (uint32_t)(
                    (ks * 16 + l15) * 272 + (wn * 64 + nt4 * 16 + hi8) * 2);
                LDSM4T(b[0], b[1], b[2], b[3], addr);
                MMA16(acc[0][nt4 * 2 + 0], a[0], b[0], b[1]);
                MMA16(acc[1][nt4 * 2 + 0], a[1], b[0], b[1]);
                MMA16(acc[0][nt4 * 2 + 1], a[0], b[2], b[3]);
                MMA16(acc[1][nt4 * 2 + 1], a[1], b[2], b[3]);
            }
        }
        __syncthreads();
    }

    // ---- epilogue ----
    #pragma unroll
    for (int mt = 0; mt < 2; mt++) {
        #pragma unroll
        for (int half_ = 0; half_ < 2; half_++) {
            int row = bm + wm * 32 + mt * 16 + r + half_ * 8;
            int bnum = row >> 11;            // / Lv
            int l    = row & (Lv - 1);
            #pragma unroll
            for (int nt = 0; nt < 8; nt++) {
                int col = bn + wn * 64 + nt * 8 + 2 * t;
                float v0 = acc[mt][nt][half_ * 2 + 0] + bias[col];
                float v1 = acc[mt][nt][half_ * 2 + 1] + bias[col + 1];
                if (ACT == 1) {
                    v0 = v0 / (1.f + __expf(-1.702f * v0));
                    v1 = v1 / (1.f + __expf(-1.702f * v1));
                }
                if (ACT == 2) {
                    float* Y = (float*)Yv;
                    size_t o0 = ((size_t)(bnum * Cv + col)) * Lv + l;
                    Y[o0]      = xres[o0]      + v0;
                    Y[o0 + Lv] = xres[o0 + Lv] + v1;
                } else {
                    __half* Y = (__half*)Yv;
                    *(__half2*)(Y + (size_t)row * N + col) = __floats2half2_rn(v0, v1);
                }
            }
        }
    }
}

// ---------------- KS=3 windowed attention (fp16 I/O, fp32 math) -----------
__global__ void attn_kernel(const __half* __restrict__ Q, const __half* __restrict__ K,
                            const __half* __restrict__ V, __half* __restrict__ O)
{
    int idx = blockIdx.x * blockDim.x + threadIdx.x;
    int h = idx & (Hv - 1);
    int l = (idx >> 3) & (Lv - 1);
    int b = idx >> 14;

    size_t rowc = ((size_t)(b * Lv + l)) * Cv + h * Dhv;
    int lm = (l > 0)      ? l - 1 : l;
    int lp = (l < Lv - 1) ? l + 1 : l;
    size_t rowm = ((size_t)(b * Lv + lm)) * Cv + h * Dhv;
    size_t rowp = ((size_t)(b * Lv + lp)) * Cv + h * Dhv;

    const uint4* q4 = (const uint4*)(Q + rowc);   // 8 x (8 halfs)
    const uint4* ka = (const uint4*)(K + rowm);
    const uint4* kb = (const uint4*)(K + rowc);
    const uint4* kc = (const uint4*)(K + rowp);

    float s0 = 0.f, s1 = 0.f, s2 = 0.f;
    #pragma unroll
    for (int i = 0; i < 8; i++) {
        uint4 qv = q4[i], av = ka[i], bv = kb[i], cv = kc[i];
        const __half2* qh = (const __half2*)&qv;
        const __half2* ah = (const __half2*)&av;
        const __half2* bh = (const __half2*)&bv;
        const __half2* ch = (const __half2*)&cv;
        #pragma unroll
        for (int j = 0; j < 4; j++) {
            float2 qf = __half22float2(qh[j]);
            float2 af = __half22float2(ah[j]);
            float2 bf = __half22float2(bh[j]);
            float2 cf = __half22float2(ch[j]);
            s0 += qf.x * af.x + qf.y * af.y;
            s1 += qf.x * bf.x + qf.y * bf.y;
            s2 += qf.x * cf.x + qf.y * cf.y;
        }
    }
    const float sc = 0.125f;
    s0 = (l > 0)      ? s0 * sc : -1e9f;
    s1 = s1 * sc;
    s2 = (l < Lv - 1) ? s2 * sc : -1e9f;
    float mx = fmaxf(s1, fmaxf(s0, s2));
    float e0 = expf(s0 - mx), e1 = expf(s1 - mx), e2 = expf(s2 - mx);
    float inv = 1.f / (e0 + e1 + e2);
    e0 *= inv; e1 *= inv; e2 *= inv;

    const uint4* va = (const uint4*)(V + rowm);
    const uint4* vb = (const uint4*)(V + rowc);
    const uint4* vc = (const uint4*)(V + rowp);
    uint4* o4 = (uint4*)(O + rowc);
    #pragma unroll
    for (int i = 0; i < 8; i++) {
        uint4 av = va[i], bv = vb[i], cv = vc[i], ov;
        const __half2* ah = (const __half2*)&av;
        const __half2* bh = (const __half2*)&bv;
        const __half2* ch = (const __half2*)&cv;
        __half2* oh = (__half2*)&ov;
        #pragma unroll
        for (int j = 0; j < 4; j++) {
            float2 af = __half22float2(ah[j]);
            float2 bf = __half22float2(bh[j]);
            float2 cf = __half22float2(ch[j]);
            oh[j] = __floats2half2_rn(e0 * af.x + e1 * bf.x + e2 * cf.x,
                                      e0 * af.y + e1 * bf.y + e2 * cf.y);
        }
        o4[i] = ov;
    }
}

// ---------------- launch ---------------------------------------------------
extern "C" void kernel_launch(void* const* d_in, const int* in_sizes, int n_in,
                              void* d_out, int out_size)
{
    const float* q   = (const float*)d_in[0];
    const float* x   = (const float*)d_in[1];
    const float* g1  = (const float*)d_in[2];
    const float* b1  = (const float*)d_in[3];
    const float* Wq  = (const float*)d_in[4];
    const float* bq  = (const float*)d_in[5];
    const float* Wk  = (const float*)d_in[6];
    const float* bk  = (const float*)d_in[7];
    const float* Wv  = (const float*)d_in[8];
    const float* bv  = (const float*)d_in[9];
    const float* Wo  = (const float*)d_in[10];
    const float* bo  = (const float*)d_in[11];
    const float* g2  = (const float*)d_in[12];
    const float* b2  = (const float*)d_in[13];
    const float* Wfc = (const float*)d_in[14];
    const float* bfc = (const float*)d_in[15];
    const float* Wpr = (const float*)d_in[16];
    const float* bpr = (const float*)d_in[17];
    float* out = (float*)d_out;

    __half *QT, *XT, *Qb, *Kb, *Vb, *Ob, *Yb, *Ub, *WT;
    float *S1, *T1, *S2, *T2;
    cudaGetSymbolAddress((void**)&QT, g_QT);
    cudaGetSymbolAddress((void**)&XT, g_XT);
    cudaGetSymbolAddress((void**)&Qb, g_Q);
    cudaGetSymbolAddress((void**)&Kb, g_K);
    cudaGetSymbolAddress((void**)&Vb, g_V);
    cudaGetSymbolAddress((void**)&Ob, g_O);
    cudaGetSymbolAddress((void**)&Yb, g_Y);
    cudaGetSymbolAddress((void**)&Ub, g_U);
    cudaGetSymbolAddress((void**)&WT, g_WT);
    cudaGetSymbolAddress((void**)&S1, g_S1);
    cudaGetSymbolAddress((void**)&T1, g_T1);
    cudaGetSymbolAddress((void**)&S2, g_S2);
    cudaGetSymbolAddress((void**)&T2, g_T2);

    cudaFuncSetAttribute(mma_gemm<0>, cudaFuncAttributeMaxDynamicSharedMemorySize, SMEM_GEMM);
    cudaFuncSetAttribute(mma_gemm<1>, cudaFuncAttributeMaxDynamicSharedMemorySize, SMEM_GEMM);
    cudaFuncSetAttribute(mma_gemm<2>, cudaFuncAttributeMaxDynamicSharedMemorySize, SMEM_GEMM);

    // 1) norm1 stats + staging transposes (norm fused, fp16 out)
    rowstats_kernel<<<Bv * Cv, 256>>>(x, g1, b1, S1, T1);
    dim3 tin_g(Lv / 32, Cv / 32, Bv), tin_b(32, 8);
    transpose_in<<<tin_g, tin_b>>>(q, nullptr, nullptr, QT);
    transpose_in<<<tin_g, tin_b>>>(x, S1, T1, XT);

    // 2) weights -> fp16 (same [K,N] layout)
    w2h_kernel<<<(512 * 512 / 4) / 256, 256>>>(Wq,  WT + WQ_OFF);
    w2h_kernel<<<(512 * 512 / 4) / 256, 256>>>(Wk,  WT + WK_OFF);
    w2h_kernel<<<(512 * 512 / 4) / 256, 256>>>(Wv,  WT + WV_OFF);
    w2h_kernel<<<(512 * 512 / 4) / 256, 256>>>(Wo,  WT + WO_OFF);
    w2h_kernel<<<(512 * 1024 / 4) / 256, 256>>>(Wfc, WT + WFC_OFF);
    w2h_kernel<<<(1024 * 512 / 4) / 256, 256>>>(Wpr, WT + WPR_OFF);

    const int Mt = (Bv * Lv) / BM;   // 256
    dim3 g512(512 / BN, Mt), g1024(1024 / BN, Mt);

    // 3) Q/K/V projections (fp16 tensor cores)
    mma_gemm<0><<<g512, 256, SMEM_GEMM>>>(QT, WT + WQ_OFF, bq, Qb, 512, 512, nullptr);
    mma_gemm<0><<<g512, 256, SMEM_GEMM>>>(XT, WT + WK_OFF, bk, Kb, 512, 512, nullptr);
    mma_gemm<0><<<g512, 256, SMEM_GEMM>>>(XT, WT + WV_OFF, bv, Vb, 512, 512, nullptr);

    // 4) windowed attention
    attn_kernel<<<(Bv * Lv * Hv) / 256, 256>>>(Qb, Kb, Vb, Ob);

    // 5) output projection
    mma_gemm<0><<<g512, 256, SMEM_GEMM>>>(Ob, WT + WO_OFF, bo, Yb, 512, 512, nullptr);

    // 6) norm2 stats + apply in place
    colstats_kernel<<<dim3(Cv / 32, Bv), 256>>>(Yb, g2, b2, S2, T2);
    normapply_kernel<<<(Bv * Lv * Cv / 2) / 256, 256>>>(Yb, S2, T2);

    // 7) MLP: fc + QuickGELU, then proj with fused residual + transpose-out
    mma_gemm<1><<<g1024, 256, SMEM_GEMM>>>(Yb, WT + WFC_OFF, bfc, Ub, 512, 1024, nullptr);
    mma_gemm<2><<<g512, 256, SMEM_GEMM>>>(Ub, WT + WPR_OFF, bpr, out, 1024, 512, x);
}

// round 6
// speedup vs baseline: 4.8035x; 1.0721x over previous
#include <cuda_runtime.h>
#include <cuda_fp16.h>
#include <math.h>
#include <stdint.h>

// ---------------- problem constants ----------------
constexpr int Bv  = 16;
constexpr int Cv  = 512;
constexpr int Lv  = 2048;
constexpr int Hv  = 8;
constexpr int Dhv = 64;

// ---------------- fp16 mma GEMM config ----------------
constexpr int BM  = 128;
constexpr int BN  = 128;
constexpr int BKK = 32;
constexpr int A_HALFS  = BM * 40;            // 80B rows, conflict-free
constexpr int B_HALFS  = BKK * 136;          // 272B rows, conflict-free
constexpr int STAGE_BYTES = (A_HALFS + B_HALFS) * 2;   // 18944
constexpr int STAGES = 4;
constexpr int SMEM_GEMM = STAGES * STAGE_BYTES;        // 75776

// ---------------- scratch ----------------
__device__ __half g_QT[16777216];
__device__ __half g_XT[16777216];
__device__ __half g_Q[16777216];
__device__ __half g_KV[33554432];  // [M,1024]: cols 0-511 K, 512-1023 V
__device__ __half g_O[16777216];
__device__ __half g_Y[16777216];
__device__ __half g_U[33554432];
__device__ __half g_WT[2097152];
__device__ float  g_BKV[1024];
__device__ float  g_S1[Bv*Cv], g_T1[Bv*Cv];
__device__ float  g_S2[Bv*Cv], g_T2[Bv*Cv];

constexpr int WQ_OFF  = 0;
constexpr int WKV_OFF = 262144;    // interleaved [512 x 1024]
constexpr int WO_OFF  = 786432;
constexpr int WFC_OFF = 1048576;
constexpr int WPR_OFF = 1572864;

// ---------------- helpers ----------------
__device__ __forceinline__ uint32_t smem_u32(const void* p) {
    uint32_t a;
    asm("{ .reg .u64 t; cvta.to.shared.u64 t, %1; cvt.u32.u64 %0, t; }" : "=r"(a) : "l"(p));
    return a;
}
__device__ __forceinline__ void cpa16(uint32_t dst, const void* src) {
    asm volatile("cp.async.cg.shared.global [%0], [%1], 16;" :: "r"(dst), "l"(src) : "memory");
}
template<int NW>
__device__ __forceinline__ void cpwait() {
    asm volatile("cp.async.wait_group %0;" :: "n"(NW) : "memory");
}

#define LDSM4(r0, r1, r2, r3, addr)                                          \
    asm volatile("ldmatrix.sync.aligned.m8n8.x4.shared.b16 {%0,%1,%2,%3}, [%4];" \
        : "=r"(r0), "=r"(r1), "=r"(r2), "=r"(r3) : "r"(addr))

#define LDSM4T(r0, r1, r2, r3, addr)                                         \
    asm volatile("ldmatrix.sync.aligned.m8n8.x4.trans.shared.b16 {%0,%1,%2,%3}, [%4];" \
        : "=r"(r0), "=r"(r1), "=r"(r2), "=r"(r3) : "r"(addr))

#define MMA16(d, a, b0, b1)                                                  \
    asm volatile("mma.sync.aligned.m16n8k16.row.col.f32.f16.f16.f32 "        \
        "{%0,%1,%2,%3}, {%4,%5,%6,%7}, {%8,%9}, {%0,%1,%2,%3};"              \
        : "+f"((d)[0]), "+f"((d)[1]), "+f"((d)[2]), "+f"((d)[3])             \
        : "r"((a)[0]), "r"((a)[1]), "r"((a)[2]), "r"((a)[3]),                \
          "r"(b0), "r"(b1))

// ---------------- instance-norm stats over rows of x (B,C,L) -------------
__global__ void rowstats_kernel(const float* __restrict__ x,
                                const float* __restrict__ gamma,
                                const float* __restrict__ beta,
                                float* __restrict__ s, float* __restrict__ t)
{
    int row = blockIdx.x;
    const float4* p = (const float4*)(x + (size_t)row * Lv);
    float sum = 0.f, sq = 0.f;
    for (int i = threadIdx.x; i < Lv / 4; i += blockDim.x) {
        float4 v = p[i];
        sum += v.x + v.y + v.z + v.w;
        sq  += v.x*v.x + v.y*v.y + v.z*v.z + v.w*v.w;
    }
    __shared__ float ssum[8], ssq[8];
    for (int o = 16; o; o >>= 1) {
        sum += __shfl_down_sync(0xffffffffu, sum, o);
        sq  += __shfl_down_sync(0xffffffffu, sq,  o);
    }
    int wid = threadIdx.x >> 5, lane = threadIdx.x & 31;
    if (lane == 0) { ssum[wid] = sum; ssq[wid] = sq; }
    __syncthreads();
    if (wid == 0) {
        sum = lane < (blockDim.x >> 5) ? ssum[lane] : 0.f;
        sq  = lane < (blockDim.x >> 5) ? ssq[lane]  : 0.f;
        for (int o = 4; o; o >>= 1) {
            sum += __shfl_down_sync(0xffffffffu, sum, o);
            sq  += __shfl_down_sync(0xffffffffu, sq,  o);
        }
        if (lane == 0) {
            float mean = sum / (float)Lv;
            float var  = sq / (float)Lv - mean * mean;
            float rstd = rsqrtf(var + 1e-5f);
            int c = row % Cv;
            float sv = gamma[c] * rstd;
            s[row] = sv;
            t[row] = beta[c] - mean * sv;
        }
    }
}

// ---------------- instance-norm stats over columns of y (B*L, C) half ----
__global__ void colstats_kernel(const __half* __restrict__ y,
                                const float* __restrict__ gamma,
                                const float* __restrict__ beta,
                                float* __restrict__ s, float* __restrict__ t)
{
    int b  = blockIdx.y;
    int ci = threadIdx.x & 31;
    int lj = threadIdx.x >> 5;
    int c  = blockIdx.x * 32 + ci;
    const __half* base = y + (size_t)b * Lv * Cv + c;
    float sum = 0.f, sq = 0.f;
    for (int l = lj; l < Lv; l += 8) {
        float v = __half2float(base[(size_t)l * Cv]);
        sum += v; sq += v * v;
    }
    __shared__ float S[8][32], Q[8][32];
    S[lj][ci] = sum; Q[lj][ci] = sq;
    __syncthreads();
    if (lj == 0) {
        #pragma unroll
        for (int j = 1; j < 8; j++) { sum += S[j][ci]; sq += Q[j][ci]; }
        float mean = sum / (float)Lv;
        float var  = sq / (float)Lv - mean * mean;
        float rstd = rsqrtf(var + 1e-5f);
        float sv = gamma[c] * rstd;
        s[b * Cv + c] = sv;
        t[b * Cv + c] = beta[c] - mean * sv;
    }
}

// ---------------- normapply: Y = half(Y*s + t) per (b,c), in place --------
__global__ void normapply_kernel(__half* __restrict__ Y,
                                 const float* __restrict__ s,
                                 const float* __restrict__ t)
{
    int i = blockIdx.x * blockDim.x + threadIdx.x;   // half2 index
    __half2 hv = ((__half2*)Y)[i];
    float2 v = __half22float2(hv);
    int e = i * 2;
    int c = e & (Cv - 1);
    int b = e >> 20;
    const float* sb = s + b * Cv + c;
    const float* tb = t + b * Cv + c;
    v.x = v.x * sb[0] + tb[0];
    v.y = v.y * sb[1] + tb[1];
    ((__half2*)Y)[i] = __floats2half2_rn(v.x, v.y);
}

// ---------------- transpose (B,C,L) fp32 -> (B*L,C) fp16, opt affine ------
__global__ void transpose_in(const float* __restrict__ src,
                             const float* __restrict__ s,
                             const float* __restrict__ t,
                             __half* __restrict__ dst)
{
    __shared__ float sm[32][33];
    int b  = blockIdx.z;
    int c0 = blockIdx.y * 32;
    int l0 = blockIdx.x * 32;
    int tx = threadIdx.x, ty = threadIdx.y;
    #pragma unroll
    for (int i = 0; i < 4; i++) {
        int c = c0 + ty + i * 8;
        float v = src[((size_t)(b * Cv + c)) * Lv + l0 + tx];
        if (s) v = v * s[b * Cv + c] + t[b * Cv + c];
        sm[ty + i * 8][tx] = v;
    }
    __syncthreads();
    #pragma unroll
    for (int i = 0; i < 4; i++) {
        int l = l0 + ty + i * 8;
        dst[((size_t)(b * Lv + l)) * Cv + c0 + tx] = __float2half(sm[tx][ty + i * 8]);
    }
}

// ---------------- all weights fp32 -> fp16 in one pass --------------------
// Wk/Wv interleaved into combined [512 x 1024]; also concats bk|bv.
__global__ void w2h_all(const float* __restrict__ Wq, const float* __restrict__ Wk,
                        const float* __restrict__ Wv, const float* __restrict__ Wo,
                        const float* __restrict__ Wfc, const float* __restrict__ Wpr,
                        const float* __restrict__ bk, const float* __restrict__ bv,
                        __half* __restrict__ WT, float* __restrict__ bkv)
{
    int i = blockIdx.x * blockDim.x + threadIdx.x;   // float4 index, 524288 total
    if (i < 1024) bkv[i] = (i < 512) ? bk[i] : bv[i - 512];
    const float* src; size_t dsth;
    if (i < 65536)       { src = Wq + (size_t)i * 4;  dsth = WQ_OFF + (size_t)i * 4; }
    else if (i < 131072) { int rel = i - 65536;  int k = rel >> 7, n4 = rel & 127;
                           src = Wk + (size_t)rel * 4;
                           dsth = WKV_OFF + (size_t)k * 1024 + n4 * 4; }
    else if (i < 196608) { int rel = i - 131072; int k = rel >> 7, n4 = rel & 127;
                           src = Wv + (size_t)rel * 4;
                           dsth = WKV_OFF + (size_t)k * 1024 + 512 + n4 * 4; }
    else if (i < 262144) { int rel = i - 196608; src = Wo + (size_t)rel * 4;
                           dsth = WO_OFF + (size_t)rel * 4; }
    else if (i < 393216) { int rel = i - 262144; src = Wfc + (size_t)rel * 4;
                           dsth = WFC_OFF + (size_t)rel * 4; }
    else                 { int rel = i - 393216; src = Wpr + (size_t)rel * 4;
                           dsth = WPR_OFF + (size_t)rel * 4; }
    float4 v = *(const float4*)src;
    *(__half2*)(WT + dsth)     = __floats2half2_rn(v.x, v.y);
    *(__half2*)(WT + dsth + 2) = __floats2half2_rn(v.z, v.w);
}

// ---------------- fp16 mma.sync GEMM with coalesced smem epilogue ---------
// Y = act( A[M,K]h @ W[K,N]h + bias_f )
// ACT 0: none (half out)  ACT 1: QuickGELU (half out)
// ACT 2: residual + transpose to (B,C,L) f32 out
template<int ACT>
__global__ void __launch_bounds__(256)
mma_gemm(const __half* __restrict__ A, const __half* __restrict__ W,
         const float* __restrict__ bias, void* __restrict__ Yv,
         int K, int N, const float* __restrict__ xres)
{
    extern __shared__ __align__(16) char smem[];
    const int tid  = threadIdx.x;
    const int bm   = blockIdx.y * BM;
    const int bn   = blockIdx.x * BN;
    const int lane = tid & 31, warp = tid >> 5;
    const int wm   = warp & 3, wn = warp >> 2;
    const int r    = lane >> 2, t = lane & 3;
    const uint32_t sbase = smem_u32(smem);
    const int nch = K / BKK;

    float acc[2][8][4];
    #pragma unroll
    for (int mt = 0; mt < 2; mt++)
        #pragma unroll
        for (int nt = 0; nt < 8; nt++)
            #pragma unroll
            for (int j = 0; j < 4; j++) acc[mt][nt][j] = 0.f;

    auto issue = [&](int c) {
        uint32_t as = sbase + (uint32_t)((c % STAGES) * STAGE_BYTES);
        uint32_t bs = as + A_HALFS * 2;
        const __half* ga = A + (size_t)bm * K + c * BKK;
        #pragma unroll
        for (int i = 0; i < 2; i++) {
            int id = tid + i * 256;
            int m = id >> 2, q = id & 3;
            cpa16(as + (uint32_t)(m * 80 + q * 16),
                  ga + (size_t)m * K + q * 8);
        }
        const __half* gb = W + (size_t)(c * BKK) * N + bn;
        #pragma unroll
        for (int i = 0; i < 2; i++) {
            int id = tid + i * 256;
            int k = id >> 4, q = id & 15;
            cpa16(bs + (uint32_t)(k * 272 + q * 16),
                  gb + (size_t)k * N + q * 8);
        }
        asm volatile("cp.async.commit_group;" ::: "memory");
    };

    issue(0); issue(1); issue(2);

    const int l15 = lane & 15;
    const int hi8 = (lane >> 4) << 3;

    for (int c = 0; c < nch; c++) {
        if (c + 2 < nch)      cpwait<2>();
        else if (c + 1 < nch) cpwait<1>();
        else                  cpwait<0>();
        __syncthreads();
        if (c + 3 < nch) issue(c + 3);

        uint32_t as = sbase + (uint32_t)((c % STAGES) * STAGE_BYTES);
        uint32_t bs = as + A_HALFS * 2;

        #pragma unroll
        for (int ks = 0; ks < 2; ks++) {
            uint32_t a[2][4];
            #pragma unroll
            for (int mt = 0; mt < 2; mt++) {
                uint32_t addr = as + (uint32_t)(
                    (wm * 32 + mt * 16 + l15) * 80 + ks * 32 + hi8 * 2);
                LDSM4(a[mt][0], a[mt][1], a[mt][2], a[mt][3], addr);
            }
            #pragma unroll
            for (int nt4 = 0; nt4 < 4; nt4++) {
                uint32_t b[4];
                uint32_t addr = bs + (uint32_t)(
                    (ks * 16 + l15) * 272 + (wn * 64 + nt4 * 16 + hi8) * 2);
                LDSM4T(b[0], b[1], b[2], b[3], addr);
                MMA16(acc[0][nt4 * 2 + 0], a[0], b[0], b[1]);
                MMA16(acc[1][nt4 * 2 + 0], a[1], b[0], b[1]);
                MMA16(acc[0][nt4 * 2 + 1], a[0], b[2], b[3]);
                MMA16(acc[1][nt4 * 2 + 1], a[1], b[2], b[3]);
            }
        }
        __syncthreads();
    }
    // all warps past final sync; smem is free for epilogue staging

    if (ACT == 2) {
        // ---- stage fp32 tile transposed: smf[c][l], stride 132 ----
        float* smf = (float*)smem;
        #pragma unroll
        for (int mt = 0; mt < 2; mt++)
            #pragma unroll
            for (int half_ = 0; half_ < 2; half_++) {
                int lrow = wm * 32 + mt * 16 + r + half_ * 8;
                #pragma unroll
                for (int nt = 0; nt < 8; nt++) {
                    int col = wn * 64 + nt * 8 + 2 * t;
                    smf[col * 132 + lrow]       = acc[mt][nt][half_ * 2 + 0] + bias[bn + col];
                    smf[(col + 1) * 132 + lrow] = acc[mt][nt][half_ * 2 + 1] + bias[bn + col + 1];
                }
            }
        __syncthreads();
        // ---- coalesced write: out[(b*Cv + bn+c)*Lv + l0 + l] = xres + val
        float* out = (float*)Yv;
        int bnum = bm >> 11;
        int l0   = bm & (Lv - 1);
        int lq = tid & 7, ci = tid >> 3;      // 8 lanes cover 128B along l
        #pragma unroll
        for (int it = 0; it < 4; it++) {
            int cc = ci + it * 32;
            const float* srow = smf + cc * 132;
            size_t gb = ((size_t)(bnum * Cv + bn + cc)) * Lv + l0;
            float4* drow = (float4*)(out + gb);
            const float4* xrow = (const float4*)(xres + gb);
            #pragma unroll
            for (int k = 0; k < 4; k++) {
                int idx = lq + k * 8;
                float4 sv = *(const float4*)(srow + idx * 4);
                float4 xv = xrow[idx];
                sv.x += xv.x; sv.y += xv.y; sv.z += xv.z; sv.w += xv.w;
                drow[idx] = sv;
            }
        }
    } else {
        // ---- stage fp16 tile: smh[m][n], stride 136 halfs ----
        __half* smh = (__half*)smem;
        #pragma unroll
        for (int mt = 0; mt < 2; mt++)
            #pragma unroll
            for (int half_ = 0; half_ < 2; half_++) {
                int lrow = wm * 32 + mt * 16 + r + half_ * 8;
                #pragma unroll
                for (int nt = 0; nt < 8; nt++) {
                    int col = wn * 64 + nt * 8 + 2 * t;
                    float v0 = acc[mt][nt][half_ * 2 + 0] + bias[bn + col];
                    float v1 = acc[mt][nt][half_ * 2 + 1] + bias[bn + col + 1];
                    if (ACT == 1) {
                        v0 = v0 / (1.f + __expf(-1.702f * v0));
                        v1 = v1 / (1.f + __expf(-1.702f * v1));
                    }
                    *(__half2*)(smh + lrow * 136 + col) = __floats2half2_rn(v0, v1);
                }
            }
        __syncthreads();
        // ---- coalesced write: 128 rows x 256B ----
        __half* Y = (__half*)Yv;
        int lq = tid & 7, mi = tid >> 3;
        #pragma unroll
        for (int it = 0; it < 4; it++) {
            int m = mi + it * 32;
            const uint4* srow = (const uint4*)(smh + m * 136);
            uint4* drow = (uint4*)(Y + (size_t)(bm + m) * N + bn);
            drow[lq]     = srow[lq];
            drow[lq + 8] = srow[lq + 8];
        }
    }
}

// ---------------- KS=3 windowed attention (K/V combined buffer) -----------
__global__ void attn_kernel(const __half* __restrict__ Q, const __half* __restrict__ KV,
                            __half* __restrict__ O)
{
    int idx = blockIdx.x * blockDim.x + threadIdx.x;
    int h = idx & (Hv - 1);
    int l = (idx >> 3) & (Lv - 1);
    int b = idx >> 14;

    size_t rowq = ((size_t)(b * Lv + l)) * Cv + h * Dhv;
    int lm = (l > 0)      ? l - 1 : l;
    int lp = (l < Lv - 1) ? l + 1 : l;
    size_t kvc = ((size_t)(b * Lv + l))  * 1024 + h * Dhv;
    size_t kvm = ((size_t)(b * Lv + lm)) * 1024 + h * Dhv;
    size_t kvp = ((size_t)(b * Lv + lp)) * 1024 + h * Dhv;

    const uint4* q4 = (const uint4*)(Q + rowq);
    const uint4* ka = (const uint4*)(KV + kvm);
    const uint4* kb = (const uint4*)(KV + kvc);
    const uint4* kc = (const uint4*)(KV + kvp);

    float s0 = 0.f, s1 = 0.f, s2 = 0.f;
    #pragma unroll
    for (int i = 0; i < 8; i++) {
        uint4 qv = q4[i], av = ka[i], bv = kb[i], cv = kc[i];
        const __half2* qh = (const __half2*)&qv;
        const __half2* ah = (const __half2*)&av;
        const __half2* bh = (const __half2*)&bv;
        const __half2* ch = (const __half2*)&cv;
        #pragma unroll
        for (int j = 0; j < 4; j++) {
            float2 qf = __half22float2(qh[j]);
            float2 af = __half22float2(ah[j]);
            float2 bf = __half22float2(bh[j]);
            float2 cf = __half22float2(ch[j]);
            s0 += qf.x * af.x + qf.y * af.y;
            s1 += qf.x * bf.x + qf.y * bf.y;
            s2 += qf.x * cf.x + qf.y * cf.y;
        }
    }
    const float sc = 0.125f;
    s0 = (l > 0)      ? s0 * sc : -1e9f;
    s1 = s1 * sc;
    s2 = (l < Lv - 1) ? s2 * sc : -1e9f;
    float mx = fmaxf(s1, fmaxf(s0, s2));
    float e0 = expf(s0 - mx), e1 = expf(s1 - mx), e2 = expf(s2 - mx);
    float inv = 1.f / (e0 + e1 + e2);
    e0 *= inv; e1 *= inv; e2 *= inv;

    const uint4* va = (const uint4*)(KV + kvm + 512);
    const uint4* vb = (const uint4*)(KV + kvc + 512);
    const uint4* vc = (const uint4*)(KV + kvp + 512);
    uint4* o4 = (uint4*)(O + rowq);
    #pragma unroll
    for (int i = 0; i < 8; i++) {
        uint4 av = va[i], bv = vb[i], cv = vc[i], ov;
        const __half2* ah = (const __half2*)&av;
        const __half2* bh = (const __half2*)&bv;
        const __half2* ch = (const __half2*)&cv;
        __half2* oh = (__half2*)&ov;
        #pragma unroll
        for (int j = 0; j < 4; j++) {
            float2 af = __half22float2(ah[j]);
            float2 bf = __half22float2(bh[j]);
            float2 cf = __half22float2(ch[j]);
            oh[j] = __floats2half2_rn(e0 * af.x + e1 * bf.x + e2 * cf.x,
                                      e0 * af.y + e1 * bf.y + e2 * cf.y);
        }
        o4[i] = ov;
    }
}

// ---------------- launch ---------------------------------------------------
extern "C" void kernel_launch(void* const* d_in, const int* in_sizes, int n_in,
                              void* d_out, int out_size)
{
    const float* q   = (const float*)d_in[0];
    const float* x   = (const float*)d_in[1];
    const float* g1  = (const float*)d_in[2];
    const float* b1  = (const float*)d_in[3];
    const float* Wq  = (const float*)d_in[4];
    const float* bq  = (const float*)d_in[5];
    const float* Wk  = (const float*)d_in[6];
    const float* bk  = (const float*)d_in[7];
    const float* Wv  = (const float*)d_in[8];
    const float* bv  = (const float*)d_in[9];
    const float* Wo  = (const float*)d_in[10];
    const float* bo  = (const float*)d_in[11];
    const float* g2  = (const float*)d_in[12];
    const float* b2  = (const float*)d_in[13];
    const float* Wfc = (const float*)d_in[14];
    const float* bfc = (const float*)d_in[15];
    const float* Wpr = (const float*)d_in[16];
    const float* bpr = (const float*)d_in[17];
    float* out = (float*)d_out;

    __half *QT, *XT, *Qb, *KVb, *Ob, *Yb, *Ub, *WT;
    float *BKV, *S1, *T1, *S2, *T2;
    cudaGetSymbolAddress((void**)&QT,  g_QT);
    cudaGetSymbolAddress((void**)&XT,  g_XT);
    cudaGetSymbolAddress((void**)&Qb,  g_Q);
    cudaGetSymbolAddress((void**)&KVb, g_KV);
    cudaGetSymbolAddress((void**)&Ob,  g_O);
    cudaGetSymbolAddress((void**)&Yb,  g_Y);
    cudaGetSymbolAddress((void**)&Ub,  g_U);
    cudaGetSymbolAddress((void**)&WT,  g_WT);
    cudaGetSymbolAddress((void**)&BKV, g_BKV);
    cudaGetSymbolAddress((void**)&S1,  g_S1);
    cudaGetSymbolAddress((void**)&T1,  g_T1);
    cudaGetSymbolAddress((void**)&S2,  g_S2);
    cudaGetSymbolAddress((void**)&T2,  g_T2);

    cudaFuncSetAttribute(mma_gemm<0>, cudaFuncAttributeMaxDynamicSharedMemorySize, SMEM_GEMM);
    cudaFuncSetAttribute(mma_gemm<1>, cudaFuncAttributeMaxDynamicSharedMemorySize, SMEM_GEMM);
    cudaFuncSetAttribute(mma_gemm<2>, cudaFuncAttributeMaxDynamicSharedMemorySize, SMEM_GEMM);

    // 1) norm1 stats + staging transposes + weight conversion
    rowstats_kernel<<<Bv * Cv, 256>>>(x, g1, b1, S1, T1);
    dim3 tin_g(Lv / 32, Cv / 32, Bv), tin_b(32, 8);
    transpose_in<<<tin_g, tin_b>>>(q, nullptr, nullptr, QT);
    transpose_in<<<tin_g, tin_b>>>(x, S1, T1, XT);
    w2h_all<<<2048, 256>>>(Wq, Wk, Wv, Wo, Wfc, Wpr, bk, bv, WT, BKV);

    const int Mt = (Bv * Lv) / BM;   // 256
    dim3 g512(512 / BN, Mt), g1024(1024 / BN, Mt);

    // 2) projections: Q (N=512), fused K|V (N=1024)
    mma_gemm<0><<<g512, 256, SMEM_GEMM>>>(QT, WT + WQ_OFF, bq, Qb, 512, 512, nullptr);
    mma_gemm<0><<<g1024, 256, SMEM_GEMM>>>(XT, WT + WKV_OFF, BKV, KVb, 512, 1024, nullptr);

    // 3) windowed attention
    attn_kernel<<<(Bv * Lv * Hv) / 256, 256>>>(Qb, KVb, Ob);

    // 4) output projection
    mma_gemm<0><<<g512, 256, SMEM_GEMM>>>(Ob, WT + WO_OFF, bo, Yb, 512, 512, nullptr);

    // 5) norm2 stats + apply in place
    colstats_kernel<<<dim3(Cv / 32, Bv), 256>>>(Yb, g2, b2, S2, T2);
    normapply_kernel<<<(Bv * Lv * Cv / 2) / 256, 256>>>(Yb, S2, T2);

    // 6) MLP: fc + QuickGELU, then proj with fused residual + transpose-out
    mma_gemm<1><<<g1024, 256, SMEM_GEMM>>>(Yb, WT + WFC_OFF, bfc, Ub, 512, 1024, nullptr);
    mma_gemm<2><<<g512, 256, SMEM_GEMM>>>(Ub, WT + WPR_OFF, bpr, out, 1024, 512, x);
}